// round 9
// baseline (speedup 1.0000x reference)
#include <cuda_runtime.h>
#include <cstdint>

// Problem constants
#define Bsz   4
#define Sseq  2048
#define Dmod  512
#define Hn    8
#define NROWS (Bsz * Sseq)        // 8192
#define QKSCALE 0.125f            // 1/sqrt(64)
#define EPSV 1e-8f

// Scratch (device globals; no allocations allowed)
__device__ float g_fused[(size_t)NROWS * Dmod];
__device__ float g_Q[(size_t)NROWS * Dmod];   // head-split layout [B,H,S,HD]
__device__ float g_K[(size_t)NROWS * Dmod];
__device__ float g_V[(size_t)NROWS * Dmod];
__device__ float g_att[(size_t)NROWS * Dmod]; // [B,S,D]

// ---------------------------------------------------------------------------
// Helpers
// ---------------------------------------------------------------------------
__device__ __forceinline__ uint32_t f2tf(float f) {
    uint32_t u;
    asm("cvt.rna.tf32.f32 %0, %1;" : "=r"(u) : "f"(f));
    return u;
}

__device__ __forceinline__ void mma8(float d[4], const uint32_t a[4], const uint32_t b[2]) {
    asm volatile(
        "mma.sync.aligned.m16n8k8.row.col.f32.tf32.tf32.f32 "
        "{%0,%1,%2,%3}, {%4,%5,%6,%7}, {%8,%9}, {%0,%1,%2,%3};"
        : "+f"(d[0]), "+f"(d[1]), "+f"(d[2]), "+f"(d[3])
        : "r"(a[0]), "r"(a[1]), "r"(a[2]), "r"(a[3]), "r"(b[0]), "r"(b[1]));
}

// ---------------------------------------------------------------------------
// Software-pipelined TF32 GEMM.
//   C[8192 x NOUT] = A[8192 x KTOT] @ W + bias
// Block tile 128x128, k-step 32, DOUBLE-BUFFERED smem + register prefetch,
// one __syncthreads per k-iteration.
// MODE 0: plain output [row*512 + c]
// MODE 1: head-split scatter to C1
// MODE 2: merged dual output (N=1024): tiles n0<512 -> (W1,b1,C1), else
//         (W2,b2,C2), both head-split.
// Smem pads: As stride 36 (frag bank = 4g+tg), Bs stride 136 (8tg+g).
// ---------------------------------------------------------------------------
template <int KTOT, int MODE>
__global__ __launch_bounds__(256, 2) void gemm_tf32(
    const float* __restrict__ A1, const float* __restrict__ A2,
    const float* __restrict__ W1, const float* __restrict__ W2,
    const float* __restrict__ b1, const float* __restrict__ b2,
    float* __restrict__ C1, float* __restrict__ C2)
{
    extern __shared__ uint32_t smg[];
    uint32_t* As = smg;                 // 2 x 128*36
    uint32_t* Bs = smg + 2 * 128 * 36;  // 2 x 32*136

    const int tid = threadIdx.x;
    const int wid = tid >> 5;
    const int lane = tid & 31;
    const int g = lane >> 2;
    const int tg = lane & 3;
    const int wm = (wid & 3) * 32;
    const int wn = (wid >> 2) * 64;
    const int m0 = blockIdx.y * 128;
    const int n0 = blockIdx.x * 128;

    const bool sel = (MODE == 2) && (n0 >= 512);
    const float* W = sel ? W2 : W1;
    const float* bias = sel ? b2 : b1;
    float* C = sel ? C2 : C1;
    const int nc = (MODE == 2) ? (n0 & 511) : n0;

    float acc[2][8][4];
#pragma unroll
    for (int mi = 0; mi < 2; mi++)
#pragma unroll
        for (int nt = 0; nt < 8; nt++)
#pragma unroll
            for (int e = 0; e < 4; e++) acc[mi][nt][e] = 0.0f;

    float4 ra[4], rb[4];

    auto ldg = [&](int kt) {
        const float* Asrc = (KTOT > 512 && kt >= 512) ? A2 : A1;
        const int kc = kt & 511;
#pragma unroll
        for (int it = 0; it < 4; it++) {
            int l = tid + it * 256;
            int r = l >> 3, c4 = l & 7;
            ra[it] = *(const float4*)&Asrc[(size_t)(m0 + r) * 512 + kc + c4 * 4];
            int kb = l >> 5, cb = l & 31;
            rb[it] = *(const float4*)&W[(size_t)(kt + kb) * 512 + nc + cb * 4];
        }
    };
    auto sts = [&](int buf) {
        uint32_t* Ab = As + buf * 128 * 36;
        uint32_t* Bb = Bs + buf * 32 * 136;
#pragma unroll
        for (int it = 0; it < 4; it++) {
            int l = tid + it * 256;
            int r = l >> 3, c4 = l & 7;
            *(uint4*)&Ab[r * 36 + c4 * 4] =
                make_uint4(f2tf(ra[it].x), f2tf(ra[it].y), f2tf(ra[it].z), f2tf(ra[it].w));
            int kb = l >> 5, cb = l & 31;
            *(uint4*)&Bb[kb * 136 + cb * 4] =
                make_uint4(f2tf(rb[it].x), f2tf(rb[it].y), f2tf(rb[it].z), f2tf(rb[it].w));
        }
    };
    auto comp = [&](int buf) {
        uint32_t* Ab = As + buf * 128 * 36;
        uint32_t* Bb = Bs + buf * 32 * 136;
#pragma unroll
        for (int ks = 0; ks < 4; ks++) {
            const int kk = ks * 8;
            uint32_t af[2][4];
#pragma unroll
            for (int mi = 0; mi < 2; mi++) {
                int rbse = wm + mi * 16 + g;
                af[mi][0] = Ab[rbse * 36 + kk + tg];
                af[mi][1] = Ab[(rbse + 8) * 36 + kk + tg];
                af[mi][2] = Ab[rbse * 36 + kk + tg + 4];
                af[mi][3] = Ab[(rbse + 8) * 36 + kk + tg + 4];
            }
#pragma unroll
            for (int nt = 0; nt < 8; nt++) {
                uint32_t bf[2];
                bf[0] = Bb[(kk + tg) * 136 + wn + nt * 8 + g];
                bf[1] = Bb[(kk + tg + 4) * 136 + wn + nt * 8 + g];
                mma8(acc[0][nt], af[0], bf);
                mma8(acc[1][nt], af[1], bf);
            }
        }
    };

    // Prologue
    ldg(0);
    sts(0);
    __syncthreads();
    int buf = 0;

#pragma unroll 2
    for (int kt = 0; kt < KTOT; kt += 32) {
        const bool more = (kt + 32) < KTOT;
        if (more) ldg(kt + 32);       // prefetch next tile (hides under compute)
        comp(buf);
        if (more) {
            sts(buf ^ 1);
            __syncthreads();
            buf ^= 1;
        }
    }

    // Epilogue (+bias, optional head-split scatter)
#pragma unroll
    for (int mi = 0; mi < 2; mi++) {
        int r0 = m0 + wm + mi * 16 + g;
#pragma unroll
        for (int nt = 0; nt < 8; nt++) {
            int c = nc + wn + nt * 8 + tg * 2;
            float bb0 = bias[c], bb1 = bias[c + 1];
#pragma unroll
            for (int rh = 0; rh < 2; rh++) {
                int row = r0 + rh * 8;
                float v0 = acc[mi][nt][rh * 2 + 0] + bb0;
                float v1 = acc[mi][nt][rh * 2 + 1] + bb1;
                size_t idx;
                if (MODE != 0) {
                    int bb = row >> 11;
                    int s = row & 2047;
                    int hh = c >> 6;
                    int hd = c & 63;
                    idx = (((size_t)(bb * Hn + hh) * Sseq + s) << 6) + hd;
                } else {
                    idx = (size_t)row * 512 + c;
                }
                *(float2*)&C[idx] = make_float2(v0, v1);
            }
        }
    }
}

// ---------------------------------------------------------------------------
// Software-pipelined TF32 flash attention, fused mask + renormalization.
// A_bar = M*e^{s*M} / (sum_j M_j e^{s_j M_j} + eps * sum_j e^{s_j M_j}),
// fixed max = 0 (scores bounded). BQ=128, BK=64, 8 warps (16 q rows each).
// K/V double-buffered in smem; next tile's K/V LDGs and this tile's mask LDGs
// issue before the QK mma stream. One __syncthreads per k-tile.
// ---------------------------------------------------------------------------
__global__ __launch_bounds__(256, 1) void attn_tf32(const float* __restrict__ Mmask)
{
    extern __shared__ uint32_t smu[];
    uint32_t* Qs = smu;                   // 128*68
    uint32_t* Ks = Qs + 128 * 68;         // 2 x 64*68
    uint32_t* Vs = Ks + 2 * 64 * 68;      // 2 x 64*72
    uint32_t* Ps = Vs + 2 * 64 * 72;      // 128*68

    const int tid = threadIdx.x;
    const int wid = tid >> 5;
    const int lane = tid & 31;
    const int g = lane >> 2;
    const int tg = lane & 3;
    const int qw = wid * 16;

    const int h = blockIdx.x;             // h fastest -> mask L2 sharing
    const int b = blockIdx.y >> 4;
    const int qt = blockIdx.y & 15;
    const int q0 = qt * 128;
    const int bh = b * Hn + h;

    const float* Qg = g_Q + ((size_t)bh * Sseq + q0) * 64;
    const float* Kg = g_K + (size_t)bh * Sseq * 64;
    const float* Vg = g_V + (size_t)bh * Sseq * 64;
    const float* Mg = Mmask + ((size_t)b * Sseq + q0) * Sseq;

    // Q tile (pre-scaled, tf32)
#pragma unroll
    for (int it = 0; it < 8; it++) {
        int l = tid + it * 256;
        int r = l >> 4, c4 = l & 15;
        float4 v = *(const float4*)&Qg[(size_t)r * 64 + c4 * 4];
        *(uint4*)&Qs[r * 68 + c4 * 4] =
            make_uint4(f2tf(v.x * QKSCALE), f2tf(v.y * QKSCALE),
                       f2tf(v.z * QKSCALE), f2tf(v.w * QKSCALE));
    }

    float4 rk[4], rv[4];
    auto ldKV = [&](int k0) {
#pragma unroll
        for (int it = 0; it < 4; it++) {
            int l = tid + it * 256;
            int r = l >> 4, c4 = l & 15;
            rk[it] = *(const float4*)&Kg[(size_t)(k0 + r) * 64 + c4 * 4];
            rv[it] = *(const float4*)&Vg[(size_t)(k0 + r) * 64 + c4 * 4];
        }
    };
    auto stsKV = [&](int buf) {
        uint32_t* Kb = Ks + buf * 64 * 68;
        uint32_t* Vb = Vs + buf * 64 * 72;
#pragma unroll
        for (int it = 0; it < 4; it++) {
            int l = tid + it * 256;
            int r = l >> 4, c4 = l & 15;
            *(uint4*)&Kb[r * 68 + c4 * 4] =
                make_uint4(f2tf(rk[it].x), f2tf(rk[it].y), f2tf(rk[it].z), f2tf(rk[it].w));
            *(uint4*)&Vb[r * 72 + c4 * 4] =
                make_uint4(f2tf(rv[it].x), f2tf(rv[it].y), f2tf(rv[it].z), f2tf(rv[it].w));
        }
    };

    float accO[8][4];
#pragma unroll
    for (int nt = 0; nt < 8; nt++)
#pragma unroll
        for (int e = 0; e < 4; e++) accO[nt][e] = 0.0f;
    float le0 = 0.0f, le1 = 0.0f, lme0 = 0.0f, lme1 = 0.0f;

    // Prologue: tile 0 into buffer 0
    ldKV(0);
    stsKV(0);
    __syncthreads();
    int buf = 0;

    for (int t = 0; t < Sseq / 64; t++) {
        const int k0 = t * 64;
        const bool more = (t + 1) < (Sseq / 64);

        // Mask prefetch for this tile (consumed after QK mmas)
        float2 mk0[8], mk1[8];
#pragma unroll
        for (int nt = 0; nt < 8; nt++) {
            int col = k0 + nt * 8 + tg * 2;
            mk0[nt] = *(const float2*)&Mg[(size_t)(qw + g) * Sseq + col];
            mk1[nt] = *(const float2*)&Mg[(size_t)(qw + g + 8) * Sseq + col];
        }
        // K/V prefetch for next tile
        if (more) ldKV(k0 + 64);

        uint32_t* Kb = Ks + buf * 64 * 68;
        uint32_t* Vb = Vs + buf * 64 * 72;

        // QK^T: S[16 x 64] per warp
        float S[8][4];
#pragma unroll
        for (int nt = 0; nt < 8; nt++)
#pragma unroll
            for (int e = 0; e < 4; e++) S[nt][e] = 0.0f;

#pragma unroll
        for (int ds = 0; ds < 8; ds++) {
            const int kk = ds * 8;
            uint32_t a[4];
            a[0] = Qs[(qw + g) * 68 + kk + tg];
            a[1] = Qs[(qw + g + 8) * 68 + kk + tg];
            a[2] = Qs[(qw + g) * 68 + kk + tg + 4];
            a[3] = Qs[(qw + g + 8) * 68 + kk + tg + 4];
#pragma unroll
            for (int nt = 0; nt < 8; nt++) {
                uint32_t bq[2];
                bq[0] = Kb[(nt * 8 + g) * 68 + kk + tg];
                bq[1] = Kb[(nt * 8 + g) * 68 + kk + tg + 4];
                mma8(S[nt], a, bq);
            }
        }

        // Masked exp (fixed max = 0); P written to per-warp Ps slice
        float se0 = 0.0f, sp0 = 0.0f, se1 = 0.0f, sp1 = 0.0f;
#pragma unroll
        for (int nt = 0; nt < 8; nt++) {
            float m00 = mk0[nt].x, m01 = mk0[nt].y;
            float m10 = mk1[nt].x, m11 = mk1[nt].y;
            float e00 = __expf(S[nt][0] * m00);
            float e01 = __expf(S[nt][1] * m01);
            float e10 = __expf(S[nt][2] * m10);
            float e11 = __expf(S[nt][3] * m11);
            float p00 = e00 * m00, p01 = e01 * m01;
            float p10 = e10 * m10, p11 = e11 * m11;
            se0 += e00 + e01; sp0 += p00 + p01;
            se1 += e10 + e11; sp1 += p10 + p11;
            *(uint2*)&Ps[(qw + g) * 68 + nt * 8 + tg * 2] =
                make_uint2(f2tf(p00), f2tf(p01));
            *(uint2*)&Ps[(qw + g + 8) * 68 + nt * 8 + tg * 2] =
                make_uint2(f2tf(p10), f2tf(p11));
        }
#pragma unroll
        for (int o = 1; o <= 2; o <<= 1) {
            se0 += __shfl_xor_sync(0xffffffffu, se0, o);
            sp0 += __shfl_xor_sync(0xffffffffu, sp0, o);
            se1 += __shfl_xor_sync(0xffffffffu, se1, o);
            sp1 += __shfl_xor_sync(0xffffffffu, sp1, o);
        }
        le0 += se0; lme0 += sp0; le1 += se1; lme1 += sp1;

        __syncwarp();   // Ps rows are warp-private

        // PV: O[16 x 64] += P @ V
#pragma unroll
        for (int ks = 0; ks < 8; ks++) {
            const int kk = ks * 8;
            uint32_t a[4];
            a[0] = Ps[(qw + g) * 68 + kk + tg];
            a[1] = Ps[(qw + g + 8) * 68 + kk + tg];
            a[2] = Ps[(qw + g) * 68 + kk + tg + 4];
            a[3] = Ps[(qw + g + 8) * 68 + kk + tg + 4];
#pragma unroll
            for (int nt = 0; nt < 8; nt++) {
                uint32_t bv[2];
                bv[0] = Vb[(kk + tg) * 72 + nt * 8 + g];
                bv[1] = Vb[(kk + tg + 4) * 72 + nt * 8 + g];
                mma8(accO[nt], a, bv);
            }
        }

        if (more) {
            stsKV(buf ^ 1);     // buf^1 last read at tile t-1; freed by that sync
            __syncthreads();
            buf ^= 1;
        }
    }

    // Normalize and write [B,S,D]
    float inv0 = 1.0f / (lme0 + EPSV * le0);
    float inv1 = 1.0f / (lme1 + EPSV * le1);
    size_t row0 = (size_t)b * Sseq + q0 + qw + g;
    size_t row1 = row0 + 8;
#pragma unroll
    for (int nt = 0; nt < 8; nt++) {
        int col = h * 64 + nt * 8 + tg * 2;
        *(float2*)&g_att[row0 * 512 + col] =
            make_float2(accO[nt][0] * inv0, accO[nt][1] * inv0);
        *(float2*)&g_att[row1 * 512 + col] =
            make_float2(accO[nt][2] * inv1, accO[nt][3] * inv1);
    }
}

// ---------------------------------------------------------------------------
extern "C" void kernel_launch(void* const* d_in, const int* in_sizes, int n_in,
                              void* d_out, int out_size)
{
    const float* gene = (const float*)d_in[0];
    const float* expr = (const float*)d_in[1];
    const float* Mmask = (const float*)d_in[2];
    const float* Wf = (const float*)d_in[3];
    const float* bf = (const float*)d_in[4];
    const float* WQ = (const float*)d_in[5];
    const float* bQ = (const float*)d_in[6];
    const float* WK = (const float*)d_in[7];
    const float* bK = (const float*)d_in[8];
    const float* WV = (const float*)d_in[9];
    const float* bV = (const float*)d_in[10];
    const float* WO = (const float*)d_in[11];
    const float* bO = (const float*)d_in[12];
    float* out = (float*)d_out;

    float *pf, *pq, *pk, *pv, *pa;
    cudaGetSymbolAddress((void**)&pf, g_fused);
    cudaGetSymbolAddress((void**)&pq, g_Q);
    cudaGetSymbolAddress((void**)&pk, g_K);
    cudaGetSymbolAddress((void**)&pv, g_V);
    cudaGetSymbolAddress((void**)&pa, g_att);

    constexpr int GEMM_SMEM = (2 * 128 * 36 + 2 * 32 * 136) * 4;   // 71680
    constexpr int ATTN_SMEM = (128 * 68 + 2 * 64 * 68 + 2 * 64 * 72 + 128 * 68) * 4; // 141312

    static bool attr_set = false;
    if (!attr_set) {
        cudaFuncSetAttribute(gemm_tf32<1024, 0>,
                             cudaFuncAttributeMaxDynamicSharedMemorySize, GEMM_SMEM);
        cudaFuncSetAttribute(gemm_tf32<512, 0>,
                             cudaFuncAttributeMaxDynamicSharedMemorySize, GEMM_SMEM);
        cudaFuncSetAttribute(gemm_tf32<512, 1>,
                             cudaFuncAttributeMaxDynamicSharedMemorySize, GEMM_SMEM);
        cudaFuncSetAttribute(gemm_tf32<512, 2>,
                             cudaFuncAttributeMaxDynamicSharedMemorySize, GEMM_SMEM);
        cudaFuncSetAttribute(attn_tf32,
                             cudaFuncAttributeMaxDynamicSharedMemorySize, ATTN_SMEM);
        attr_set = true;
    }

    dim3 block(256);

    // fused = concat(gene, expr) @ W_fused + b_fused   (single K=1024 GEMM)
    gemm_tf32<1024, 0><<<dim3(4, 64), block, GEMM_SMEM>>>(
        gene, expr, Wf, nullptr, bf, nullptr, pf, nullptr);

    // Q and K from fused in ONE merged N=1024 GEMM (head-split outputs)
    gemm_tf32<512, 2><<<dim3(8, 64), block, GEMM_SMEM>>>(
        pf, pf, WQ, WK, bQ, bK, pq, pk);

    // V from expr (head-split)
    gemm_tf32<512, 1><<<dim3(4, 64), block, GEMM_SMEM>>>(
        expr, expr, WV, nullptr, bV, nullptr, pv, nullptr);

    // Attention (h fastest for mask L2 reuse)
    attn_tf32<<<dim3(Hn, Bsz * 16), block, ATTN_SMEM>>>(Mmask);

    // Output projection
    gemm_tf32<512, 0><<<dim3(4, 64), block, GEMM_SMEM>>>(
        pa, pa, WO, nullptr, bO, nullptr, out, nullptr);
}

// round 12
// speedup vs baseline: 1.9185x; 1.9185x over previous
#include <cuda_runtime.h>
#include <cuda_fp16.h>
#include <cstdint>

// Problem constants
#define Bsz   4
#define Sseq  2048
#define Dmod  512
#define Hn    8
#define NROWS (Bsz * Sseq)        // 8192
#define QKSCALE 0.125f            // 1/sqrt(64)
#define EPSV 1e-8f

// Scratch (device globals; no allocations allowed)
__device__ float g_fused[(size_t)NROWS * Dmod];
__device__ float g_Q[(size_t)NROWS * Dmod];   // head-split layout [B,H,S,HD]
__device__ float g_K[(size_t)NROWS * Dmod];
__device__ float g_V[(size_t)NROWS * Dmod];
__device__ float g_att[(size_t)NROWS * Dmod]; // [B,S,D]

// ---------------------------------------------------------------------------
// Helpers
// ---------------------------------------------------------------------------
__device__ __forceinline__ uint32_t f2h2(float lo, float hi) {
    __half2 h = __floats2half2_rn(lo, hi);
    return *reinterpret_cast<uint32_t*>(&h);
}

__device__ __forceinline__ uint32_t smem_u32(const void* p) {
    uint32_t a;
    asm("{ .reg .u64 t; cvta.to.shared.u64 t, %1; cvt.u32.u64 %0, t; }"
        : "=r"(a) : "l"(p));
    return a;
}

__device__ __forceinline__ void ldsm4(uint32_t r[4], uint32_t addr) {
    asm volatile("ldmatrix.sync.aligned.m8n8.x4.shared.b16 {%0,%1,%2,%3}, [%4];"
        : "=r"(r[0]), "=r"(r[1]), "=r"(r[2]), "=r"(r[3]) : "r"(addr));
}
__device__ __forceinline__ void ldsm4t(uint32_t r[4], uint32_t addr) {
    asm volatile("ldmatrix.sync.aligned.m8n8.x4.trans.shared.b16 {%0,%1,%2,%3}, [%4];"
        : "=r"(r[0]), "=r"(r[1]), "=r"(r[2]), "=r"(r[3]) : "r"(addr));
}

// m16n8k16 f16 mma, fp32 accumulate
__device__ __forceinline__ void mma16(float d[4], const uint32_t a[4],
                                      uint32_t b0, uint32_t b1) {
    asm volatile(
        "mma.sync.aligned.m16n8k16.row.col.f32.f16.f16.f32 "
        "{%0,%1,%2,%3}, {%4,%5,%6,%7}, {%8,%9}, {%0,%1,%2,%3};"
        : "+f"(d[0]), "+f"(d[1]), "+f"(d[2]), "+f"(d[3])
        : "r"(a[0]), "r"(a[1]), "r"(a[2]), "r"(a[3]), "r"(b0), "r"(b1));
}

// ---------------------------------------------------------------------------
// FP16 tensor GEMM: C[8192 x N] = A[8192 x KTOT] @ W + bias
// Block tile 128x128, k-step 32, double-buffered smem + register prefetch,
// one __syncthreads per k-iteration (R8-proven pipeline).
// A smem: [128 m][32 k] halves, row stride 80B. A frags: ldmatrix.x4.
// B smem: [32 k][128 n] halves, row stride 272B (natural coalesced store
//         from row-major W). B frags: ldmatrix.x4.trans.
// MODE 0: plain out; MODE 1: head-split; MODE 2: merged dual (n0<512 ->
// (W1,b1,C1) else (W2,b2,C2), both head-split).
// ---------------------------------------------------------------------------
#define GA_STRIDE 80          // bytes per A row (64 data + 16 pad)
#define GB_STRIDE 272         // bytes per B row (256 data + 16 pad)
#define GA_BYTES  (128 * GA_STRIDE)    // 10240
#define GB_BYTES  (32 * GB_STRIDE)     // 8704
#define G_SMEM    (2 * (GA_BYTES + GB_BYTES))   // 37888

template <int KTOT, int MODE>
__global__ __launch_bounds__(256, 2) void gemm_f16(
    const float* __restrict__ A1, const float* __restrict__ A2,
    const float* __restrict__ W1, const float* __restrict__ W2,
    const float* __restrict__ b1, const float* __restrict__ b2,
    float* __restrict__ C1, float* __restrict__ C2)
{
    extern __shared__ char smem[];
    const uint32_t sb = smem_u32(smem);
    const int tid = threadIdx.x;
    const int wid = tid >> 5;
    const int lane = tid & 31;
    const int g = lane >> 2;
    const int tg = lane & 3;
    const int wm = (wid & 3) * 32;
    const int wn = (wid >> 2) * 64;
    const int m0 = blockIdx.y * 128;
    const int n0 = blockIdx.x * 128;

    const bool selW = (MODE == 2) && (n0 >= 512);
    const float* W = selW ? W2 : W1;
    const float* bias = selW ? b2 : b1;
    float* C = selW ? C2 : C1;
    const int nc = (MODE == 2) ? (n0 & 511) : n0;

    // ldmatrix lane address components
    const int jr = (lane & 7) + ((lane >> 3) & 1) * 8;   // A rows / B-trans rows
    const int jc16 = (lane >> 4) * 16;                   // A chunk
    const int vc = (lane >> 4) * 16;                     // B-trans col byte (8 halves)

    float acc[2][8][4];
#pragma unroll
    for (int mi = 0; mi < 2; mi++)
#pragma unroll
        for (int nt = 0; nt < 8; nt++)
#pragma unroll
            for (int e = 0; e < 4; e++) acc[mi][nt][e] = 0.0f;

    float4 ra[4], rb[4];

    auto ldg = [&](int kt) {
        const float* Asrc = (KTOT > 512 && kt >= 512) ? A2 : A1;
        const int kc = kt & 511;
#pragma unroll
        for (int it = 0; it < 4; it++) {
            int l = tid + it * 256;
            int r = l >> 3, c4 = l & 7;
            ra[it] = *(const float4*)&Asrc[(size_t)(m0 + r) * 512 + kc + c4 * 4];
            int k = l >> 5, n4 = l & 31;
            rb[it] = *(const float4*)&W[(size_t)(kt + k) * 512 + nc + n4 * 4];
        }
    };
    auto sts = [&](int buf) {
        char* Ab = smem + buf * (GA_BYTES + GB_BYTES);
        char* Bb = Ab + GA_BYTES;
#pragma unroll
        for (int it = 0; it < 4; it++) {
            int l = tid + it * 256;
            int r = l >> 3, c4 = l & 7;
            *(uint2*)(Ab + r * GA_STRIDE + c4 * 8) =
                make_uint2(f2h2(ra[it].x, ra[it].y), f2h2(ra[it].z, ra[it].w));
            int k = l >> 5, n4 = l & 31;
            *(uint2*)(Bb + k * GB_STRIDE + n4 * 8) =
                make_uint2(f2h2(rb[it].x, rb[it].y), f2h2(rb[it].z, rb[it].w));
        }
    };
    auto comp = [&](int buf) {
        const uint32_t Ab = sb + buf * (GA_BYTES + GB_BYTES);
        const uint32_t Bb = Ab + GA_BYTES;
#pragma unroll
        for (int ks = 0; ks < 2; ks++) {
            uint32_t a0[4], a1[4];
            ldsm4(a0, Ab + (wm + jr) * GA_STRIDE + ks * 32 + jc16);
            ldsm4(a1, Ab + (wm + 16 + jr) * GA_STRIDE + ks * 32 + jc16);
#pragma unroll
            for (int np = 0; np < 4; np++) {
                uint32_t br[4];
                ldsm4t(br, Bb + (ks * 16 + jr) * GB_STRIDE + (wn + np * 16) * 2 + vc);
                mma16(acc[0][np * 2 + 0], a0, br[0], br[1]);
                mma16(acc[0][np * 2 + 1], a0, br[2], br[3]);
                mma16(acc[1][np * 2 + 0], a1, br[0], br[1]);
                mma16(acc[1][np * 2 + 1], a1, br[2], br[3]);
            }
        }
    };

    // Prologue
    ldg(0);
    sts(0);
    __syncthreads();
    int buf = 0;

#pragma unroll 2
    for (int kt = 0; kt < KTOT; kt += 32) {
        const bool more = (kt + 32) < KTOT;
        if (more) ldg(kt + 32);
        comp(buf);
        if (more) {
            sts(buf ^ 1);
            __syncthreads();
            buf ^= 1;
        }
    }

    // Epilogue (+bias, optional head-split scatter)
#pragma unroll
    for (int mi = 0; mi < 2; mi++) {
        int r0 = m0 + wm + mi * 16 + g;
#pragma unroll
        for (int nt = 0; nt < 8; nt++) {
            int c = nc + wn + nt * 8 + tg * 2;
            float bb0 = bias[c], bb1 = bias[c + 1];
#pragma unroll
            for (int rh = 0; rh < 2; rh++) {
                int row = r0 + rh * 8;
                float v0 = acc[mi][nt][rh * 2 + 0] + bb0;
                float v1 = acc[mi][nt][rh * 2 + 1] + bb1;
                size_t idx;
                if (MODE != 0) {
                    int bb = row >> 11;
                    int s = row & 2047;
                    int hh = c >> 6;
                    idx = (((size_t)(bb * Hn + hh) * Sseq + s) << 6) + (c & 63);
                } else {
                    idx = (size_t)row * 512 + c;
                }
                *(float2*)&C[idx] = make_float2(v0, v1);
            }
        }
    }
}

// ---------------------------------------------------------------------------
// FP16 flash attention with fused mask + renormalization.
// A_bar = M*e^{s*M} / (sum_j M_j e^{s_j M_j} + eps * sum_j e^{s_j M_j}),
// fixed max = 0 (scores bounded |s| <~ 7; P <= e^7 fits fp16).
// BQ=128 (8 warps x 16 q), BK=64.
// Qs[128][64+8]h, Ks[64][64+8]h, Vs[64][64+8]h (144B rows) = 36.9KB smem.
// QK: Q frags ldmatrix, K-as-B frags non-trans ldmatrix (k-dim = d).
// P: converted to half2 IN REGISTERS (QK accum fragment == PV A fragment).
// PV: V-as-B frags ldmatrix.trans (k-dim = seq).  No P smem round-trip.
// ---------------------------------------------------------------------------
#define AT_STRIDE 144
#define AT_Q 0
#define AT_K (128 * AT_STRIDE)
#define AT_V (AT_K + 64 * AT_STRIDE)
#define AT_SMEM (AT_V + 64 * AT_STRIDE)   // 36864

__global__ __launch_bounds__(256, 2) void attn_f16(const float* __restrict__ Mmask)
{
    extern __shared__ char smem[];
    const uint32_t sb = smem_u32(smem);
    const int tid = threadIdx.x;
    const int wid = tid >> 5;
    const int lane = tid & 31;
    const int g = lane >> 2;
    const int tg = lane & 3;
    const int qw = wid * 16;

    const int h = blockIdx.x;           // h fastest -> mask L2 sharing
    const int b = blockIdx.y >> 4;
    const int qt = blockIdx.y & 15;
    const int q0 = qt * 128;
    const int bh = b * Hn + h;

    const float* Qg = g_Q + ((size_t)bh * Sseq + q0) * 64;
    const float* Kg = g_K + (size_t)bh * Sseq * 64;
    const float* Vg = g_V + (size_t)bh * Sseq * 64;
    const float* Mg = Mmask + ((size_t)b * Sseq + q0) * Sseq;

    // ldmatrix lane address components
    const int jr = (lane & 7) + ((lane >> 3) & 1) * 8;   // A-rows / trans-rows
    const int jc16 = (lane >> 4) * 16;                   // A chunk
    const int kr = (lane & 7) + ((lane >> 4) & 1) * 8;   // K non-trans row
    const int kc = ((lane >> 3) & 1) * 16;               // K non-trans chunk
    const int vcb = (lane >> 4) * 16;                    // V trans col bytes

    // Load Q tile (pre-scaled, f16): 128 rows x 16 float4
#pragma unroll
    for (int it = 0; it < 8; it++) {
        int l = tid + it * 256;
        int r = l >> 4, c4 = l & 15;
        float4 v = *(const float4*)&Qg[(size_t)r * 64 + c4 * 4];
        *(uint2*)(smem + AT_Q + r * AT_STRIDE + c4 * 8) =
            make_uint2(f2h2(v.x * QKSCALE, v.y * QKSCALE),
                       f2h2(v.z * QKSCALE, v.w * QKSCALE));
    }

    float accO[8][4];
#pragma unroll
    for (int nt = 0; nt < 8; nt++)
#pragma unroll
        for (int e = 0; e < 4; e++) accO[nt][e] = 0.0f;
    float le0 = 0.0f, le1 = 0.0f, lme0 = 0.0f, lme1 = 0.0f;

    for (int k0 = 0; k0 < Sseq; k0 += 64) {
        __syncthreads();    // prior tile's V reads complete before overwrite

        // Mask prefetch: rows {qw+g, qw+g+8}, cols k0 + nt*8 + tg*2
        float2 mk0[8], mk1[8];
#pragma unroll
        for (int nt = 0; nt < 8; nt++) {
            int col = k0 + nt * 8 + tg * 2;
            mk0[nt] = *(const float2*)&Mg[(size_t)(qw + g) * Sseq + col];
            mk1[nt] = *(const float2*)&Mg[(size_t)(qw + g + 8) * Sseq + col];
        }

        // K, V tiles -> f16 smem (64 rows x 16 float4 each)
#pragma unroll
        for (int it = 0; it < 4; it++) {
            int l = tid + it * 256;
            int r = l >> 4, c4 = l & 15;
            float4 kv = *(const float4*)&Kg[(size_t)(k0 + r) * 64 + c4 * 4];
            *(uint2*)(smem + AT_K + r * AT_STRIDE + c4 * 8) =
                make_uint2(f2h2(kv.x, kv.y), f2h2(kv.z, kv.w));
            float4 vv = *(const float4*)&Vg[(size_t)(k0 + r) * 64 + c4 * 4];
            *(uint2*)(smem + AT_V + r * AT_STRIDE + c4 * 8) =
                make_uint2(f2h2(vv.x, vv.y), f2h2(vv.z, vv.w));
        }
        __syncthreads();

        // QK^T: S[16 x 64] per warp; k-dim = d = 64 (4 ksteps)
        float S[8][4];
#pragma unroll
        for (int nt = 0; nt < 8; nt++)
#pragma unroll
            for (int e = 0; e < 4; e++) S[nt][e] = 0.0f;

#pragma unroll
        for (int ks = 0; ks < 4; ks++) {
            uint32_t a[4];
            ldsm4(a, sb + AT_Q + (qw + jr) * AT_STRIDE + ks * 32 + jc16);
#pragma unroll
            for (int np = 0; np < 4; np++) {
                uint32_t br[4];   // r0,r1 = b0,b1 of ng=2np; r2,r3 = ng=2np+1
                ldsm4(br, sb + AT_K + (np * 16 + kr) * AT_STRIDE + ks * 32 + kc);
                mma16(S[np * 2 + 0], a, br[0], br[1]);
                mma16(S[np * 2 + 1], a, br[2], br[3]);
            }
        }

        // Masked exp (fixed max = 0); P -> half2 REGISTERS (PV A-fragments)
        uint32_t paL[8], paH[8];
        float se0 = 0.0f, sp0 = 0.0f, se1 = 0.0f, sp1 = 0.0f;
#pragma unroll
        for (int nt = 0; nt < 8; nt++) {
            float m00 = mk0[nt].x, m01 = mk0[nt].y;
            float m10 = mk1[nt].x, m11 = mk1[nt].y;
            float e00 = __expf(S[nt][0] * m00);
            float e01 = __expf(S[nt][1] * m01);
            float e10 = __expf(S[nt][2] * m10);
            float e11 = __expf(S[nt][3] * m11);
            float p00 = e00 * m00, p01 = e01 * m01;
            float p10 = e10 * m10, p11 = e11 * m11;
            se0 += e00 + e01; sp0 += p00 + p01;
            se1 += e10 + e11; sp1 += p10 + p11;
            paL[nt] = f2h2(p00, p01);
            paH[nt] = f2h2(p10, p11);
        }
#pragma unroll
        for (int o = 1; o <= 2; o <<= 1) {
            se0 += __shfl_xor_sync(0xffffffffu, se0, o);
            sp0 += __shfl_xor_sync(0xffffffffu, sp0, o);
            se1 += __shfl_xor_sync(0xffffffffu, se1, o);
            sp1 += __shfl_xor_sync(0xffffffffu, sp1, o);
        }
        le0 += se0; lme0 += sp0; le1 += se1; lme1 += sp1;

        // PV: O[16 x 64] += P[16 x 64] @ V[64 x 64]; k-dim = seq (4 ksteps)
#pragma unroll
        for (int ks = 0; ks < 4; ks++) {
            uint32_t a[4];
            a[0] = paL[ks * 2 + 0];
            a[1] = paH[ks * 2 + 0];
            a[2] = paL[ks * 2 + 1];
            a[3] = paH[ks * 2 + 1];
#pragma unroll
            for (int np = 0; np < 4; np++) {
                uint32_t br[4];
                ldsm4t(br, sb + AT_V + (ks * 16 + jr) * AT_STRIDE + np * 32 + vcb);
                mma16(accO[np * 2 + 0], a, br[0], br[1]);
                mma16(accO[np * 2 + 1], a, br[2], br[3]);
            }
        }
    }

    // Normalize and write [B,S,D]
    float inv0 = 1.0f / (lme0 + EPSV * le0);
    float inv1 = 1.0f / (lme1 + EPSV * le1);
    size_t row0 = (size_t)b * Sseq + q0 + qw + g;
    size_t row1 = row0 + 8;
#pragma unroll
    for (int nt = 0; nt < 8; nt++) {
        int col = h * 64 + nt * 8 + tg * 2;
        *(float2*)&g_att[row0 * 512 + col] =
            make_float2(accO[nt][0] * inv0, accO[nt][1] * inv0);
        *(float2*)&g_att[row1 * 512 + col] =
            make_float2(accO[nt][2] * inv1, accO[nt][3] * inv1);
    }
}

// ---------------------------------------------------------------------------
extern "C" void kernel_launch(void* const* d_in, const int* in_sizes, int n_in,
                              void* d_out, int out_size)
{
    const float* gene = (const float*)d_in[0];
    const float* expr = (const float*)d_in[1];
    const float* Mmask = (const float*)d_in[2];
    const float* Wf = (const float*)d_in[3];
    const float* bf = (const float*)d_in[4];
    const float* WQ = (const float*)d_in[5];
    const float* bQ = (const float*)d_in[6];
    const float* WK = (const float*)d_in[7];
    const float* bK = (const float*)d_in[8];
    const float* WV = (const float*)d_in[9];
    const float* bV = (const float*)d_in[10];
    const float* WO = (const float*)d_in[11];
    const float* bO = (const float*)d_in[12];
    float* out = (float*)d_out;

    float *pf, *pq, *pk, *pv, *pa;
    cudaGetSymbolAddress((void**)&pf, g_fused);
    cudaGetSymbolAddress((void**)&pq, g_Q);
    cudaGetSymbolAddress((void**)&pk, g_K);
    cudaGetSymbolAddress((void**)&pv, g_V);
    cudaGetSymbolAddress((void**)&pa, g_att);

    static bool attr_set = false;
    if (!attr_set) {
        cudaFuncSetAttribute(gemm_f16<1024, 0>,
                             cudaFuncAttributeMaxDynamicSharedMemorySize, G_SMEM);
        cudaFuncSetAttribute(gemm_f16<512, 0>,
                             cudaFuncAttributeMaxDynamicSharedMemorySize, G_SMEM);
        cudaFuncSetAttribute(gemm_f16<512, 1>,
                             cudaFuncAttributeMaxDynamicSharedMemorySize, G_SMEM);
        cudaFuncSetAttribute(gemm_f16<512, 2>,
                             cudaFuncAttributeMaxDynamicSharedMemorySize, G_SMEM);
        cudaFuncSetAttribute(attn_f16,
                             cudaFuncAttributeMaxDynamicSharedMemorySize, AT_SMEM);
        attr_set = true;
    }

    dim3 block(256);

    // fused = concat(gene, expr) @ W_fused + b_fused   (single K=1024 GEMM)
    gemm_f16<1024, 0><<<dim3(4, 64), block, G_SMEM>>>(
        gene, expr, Wf, nullptr, bf, nullptr, pf, nullptr);

    // Q and K from fused in ONE merged N=1024 GEMM (head-split outputs)
    gemm_f16<512, 2><<<dim3(8, 64), block, G_SMEM>>>(
        pf, pf, WQ, WK, bQ, bK, pq, pk);

    // V from expr (head-split)
    gemm_f16<512, 1><<<dim3(4, 64), block, G_SMEM>>>(
        expr, expr, WV, nullptr, bV, nullptr, pv, nullptr);

    // Attention (h fastest for mask L2 reuse)
    attn_f16<<<dim3(Hn, Bsz * 16), block, AT_SMEM>>>(Mmask);

    // Output projection
    gemm_f16<512, 0><<<dim3(4, 64), block, G_SMEM>>>(
        pa, pa, WO, nullptr, bO, nullptr, out, nullptr);
}